// round 9
// baseline (speedup 1.0000x reference)
#include <cuda_runtime.h>
#include <cuda_bf16.h>
#include <cstdint>
#include <stdint.h>
#include <math.h>

#define B_  32
#define CH_ 64
#define T_  2048

__device__ unsigned g_rkmax[B_ * T_];
__device__ unsigned g_rkmin[B_ * T_];
__device__ float    g_colsum[B_ * T_];
__device__ float    g_scal[4];
__device__ __nv_bfloat16 g_xbf[(size_t)B_ * CH_ * T_];

__device__ __forceinline__ unsigned fenc(float f) {
    unsigned u = __float_as_uint(f);
    return u ^ ((u >> 31) ? 0xFFFFFFFFu : 0x80000000u);
}
__device__ __forceinline__ float fdec(unsigned k) {
    unsigned u = (k >> 31) ? (k ^ 0x80000000u) : (k ^ 0xFFFFFFFFu);
    return __uint_as_float(u);
}
__device__ __forceinline__ uint32_t pk2(float a, float b) {
    __nv_bfloat162 h = __floats2bfloat162_rn(a, b);
    return *(uint32_t*)&h;
}
__device__ __forceinline__ float ex2f(float x) {
    float r;
    asm("ex2.approx.f32 %0, %1;" : "=f"(r) : "f"(x));
    return r;
}
__device__ __forceinline__ uint32_t sptr(const void* p) {
    return (uint32_t)__cvta_generic_to_shared(p);
}
__device__ __forceinline__ void cpa16(uint32_t dst, const void* src) {
    asm volatile("cp.async.cg.shared.global [%0], [%1], 16;" :: "r"(dst), "l"(src));
}
__device__ __forceinline__ void cpa_commit() {
    asm volatile("cp.async.commit_group;" ::: "memory");
}
__device__ __forceinline__ void cpa_wait0() {
    asm volatile("cp.async.wait_group 0;" ::: "memory");
}
__device__ __forceinline__ void ldsm4(uint32_t* r, uint32_t a) {
    asm volatile("ldmatrix.sync.aligned.m8n8.x4.shared.b16 {%0,%1,%2,%3}, [%4];"
        : "=r"(r[0]), "=r"(r[1]), "=r"(r[2]), "=r"(r[3]) : "r"(a));
}
__device__ __forceinline__ void ldsm4t(uint32_t* r, uint32_t a) {
    asm volatile("ldmatrix.sync.aligned.m8n8.x4.trans.shared.b16 {%0,%1,%2,%3}, [%4];"
        : "=r"(r[0]), "=r"(r[1]), "=r"(r[2]), "=r"(r[3]) : "r"(a));
}
__device__ __forceinline__ void mma16816(float* d, const uint32_t* a, const uint32_t* b) {
    asm volatile("mma.sync.aligned.m16n8k16.row.col.f32.bf16.bf16.f32 "
        "{%0,%1,%2,%3}, {%4,%5,%6,%7}, {%8,%9}, {%0,%1,%2,%3};"
        : "+f"(d[0]), "+f"(d[1]), "+f"(d[2]), "+f"(d[3])
        : "r"(a[0]), "r"(a[1]), "r"(a[2]), "r"(a[3]), "r"(b[0]), "r"(b[1]));
}

#define LDT 136   // 272B row stride

__device__ __forceinline__ uint32_t addrA(uint32_t base, int lane, int k0, int c0) {
    int k = k0 + (lane & 7) + ((lane >> 4) << 3);
    int c = c0 + (((lane >> 3) & 1) << 3);
    return base + (uint32_t)(k * LDT + c) * 2;
}
__device__ __forceinline__ uint32_t addrBt(uint32_t base, int lane, int k0, int n0) {
    int k = k0 + (lane & 7) + (((lane >> 3) & 1) << 3);
    int n = n0 + ((lane >> 4) << 3);
    return base + (uint32_t)(k * LDT + n) * 2;
}
__device__ __forceinline__ uint32_t addrBp(uint32_t base, int lane, int n0, int k0) {
    int n = n0 + (lane & 7) + ((lane >> 4) << 3);
    int k = k0 + (((lane >> 3) & 1) << 3);
    return base + (uint32_t)(n * LDT + k) * 2;
}

// ---------------------------------------------------------------------------
// Kernel 0: colsum + f32->bf16 conversion + scalars + stat init.
// ---------------------------------------------------------------------------
__global__ void precompute_kernel(const float* __restrict__ x,
                                  const float* __restrict__ w1,
                                  const float* __restrict__ b1,
                                  const float* __restrict__ w2,
                                  const float* __restrict__ b2) {
    int idx = blockIdx.x * blockDim.x + threadIdx.x;
    if (idx == 0) {
        float s = 0.f, u = 0.f, v = 0.f, w = 0.f;
#pragma unroll
        for (int f = 0; f < 8; f++) {
            s += w1[f] * w2[f];
            u += w1[f] * b2[f];
            v += b1[f] * w2[f];
            w += b1[f] * b2[f];
        }
        g_scal[0] = s; g_scal[1] = u; g_scal[2] = v; g_scal[3] = w * (float)CH_;
    }
    const int b = idx / (T_ / 2), t = (idx % (T_ / 2)) * 2;
    const size_t base = (size_t)b * CH_ * T_ + t;
    float s0 = 0.f, s1 = 0.f;
#pragma unroll 8
    for (int c = 0; c < CH_; c++) {
        float2 v2 = *(const float2*)(x + base + (size_t)c * T_);
        s0 += v2.x; s1 += v2.y;
        *(uint32_t*)(g_xbf + base + (size_t)c * T_) = pk2(v2.x, v2.y);
    }
    g_colsum[b * T_ + t]     = s0;
    g_colsum[b * T_ + t + 1] = s1;
    g_rkmax[b * T_ + t] = 0x007FFFFFu;  g_rkmax[b * T_ + t + 1] = 0x007FFFFFu;
    g_rkmin[b * T_ + t] = 0xFF800000u;  g_rkmin[b * T_ + t + 1] = 0xFF800000u;
}

// ---------------------------------------------------------------------------
// Pass 1: triangular Gram, 2 adjacent j-tiles per CTA (128i x 256j), K=64.
// Dyn smem layout:
//  As@0 17408 | Bs@17408 34816 | vcsj@52224 1024 | ucj@53248 1024 |
//  vcsi@54272 512 | uci@54784 512 | colpx@55296 2048 | colpn@57344 2048
// total 59392
// ---------------------------------------------------------------------------
#define SMEM_MM 59392

__global__ __launch_bounds__(256, 2) void minmax_pair(int pair0) {
    extern __shared__ unsigned char sm[];
    const uint32_t sa = sptr(sm), sb = sa + 17408;
    float* vcsj  = (float*)(sm + 52224);   // [256]
    float* ucj   = (float*)(sm + 53248);   // [256]
    float* vcsi  = (float*)(sm + 54272);   // [128]
    float* uci   = (float*)(sm + 54784);   // [128]
    float (*colpx)[128] = (float(*)[128])(sm + 55296);
    float (*colpn)[128] = (float(*)[128])(sm + 57344);

    const int tid = threadIdx.x, lane = tid & 31, wid = tid >> 5;
    const int b = blockIdx.y;

    // decode pair index -> (ti, tj0)
    int t = pair0 + blockIdx.x, ti = 0;
    while (t >= (17 - ti) / 2) { t -= (17 - ti) / 2; ti++; }
    const int tj0 = ti + 2 * t;
    const int has2 = (tj0 < 15);
    const int it = ti * 128, jt = tj0 * 128;
    const int n_j = has2 ? 256 : 128;

    const __nv_bfloat16* Xb = g_xbf + (size_t)b * CH_ * T_;
    const float s = g_scal[0], u = g_scal[1], v = g_scal[2], w0 = g_scal[3];

    // fills
    {
#pragma unroll
        for (int l = 0; l < 4; l++) {
            int cid = l * 256 + tid;
            int k = cid >> 4, xo = cid & 15;
            cpa16(sa + (uint32_t)(k * LDT + xo * 8) * 2, Xb + (size_t)k * T_ + it + xo * 8);
        }
#pragma unroll
        for (int l = 0; l < 8; l++) {
            int cid = l * 256 + tid;        // 2048 ids: tile = cid>>10
            int t1 = cid >> 10, r = cid & 1023;
            int k = r >> 4, xo = r & 15;
            if (t1 == 0 || has2)
                cpa16(sb + (uint32_t)(t1 * 64 * LDT + k * LDT + xo * 8) * 2,
                      Xb + (size_t)k * T_ + jt + t1 * 128 + xo * 8);
        }
        cpa_commit();
    }
    if (tid < n_j) {
        float cj = g_colsum[b * T_ + jt + tid];
        vcsj[tid] = v * cj;
        ucj[tid]  = fmaf(u, cj, w0);
    }
    if (tid < 128) {
        float ci = g_colsum[b * T_ + it + tid];
        vcsi[tid] = v * ci;
        uci[tid]  = fmaf(u, ci, w0);
    }
    cpa_wait0();
    __syncthreads();

    const int wi = wid & 3, wc = wid >> 2;
    const int i0w = wi * 32, j0w = wc * 64;
    const int g = lane >> 2, tig = lane & 3;

    // row stats held across tiles: [mb][rr]
    float rxA[2][2], rnA[2][2];
#pragma unroll
    for (int a1 = 0; a1 < 2; a1++)
#pragma unroll
        for (int a2 = 0; a2 < 2; a2++) { rxA[a1][a2] = -INFINITY; rnA[a1][a2] = INFINITY; }

    for (int t1 = 0; t1 < 2; t1++) {
        if (t1 == 1 && !has2) break;
        const uint32_t bb = sb + (uint32_t)(t1 * 64 * LDT) * 2;
        const int jo = t1 * 128;           // offset into vcsj/ucj

        float acc[16][4];
#pragma unroll
        for (int q = 0; q < 16; q++)
#pragma unroll
            for (int e = 0; e < 4; e++) acc[q][e] = 0.f;

#pragma unroll
        for (int ks = 0; ks < 4; ks++) {
            uint32_t a0[4], a1r[4];
            ldsm4t(a0,  addrA(sa, lane, ks * 16, i0w));
            ldsm4t(a1r, addrA(sa, lane, ks * 16, i0w + 16));
#pragma unroll
            for (int n16 = 0; n16 < 4; n16++) {
                uint32_t bf[4];
                ldsm4t(bf, addrBt(bb, lane, ks * 16, j0w + n16 * 16));
                mma16816(acc[n16 * 2],     a0, bf);
                mma16816(acc[n16 * 2 + 1], a0, bf + 2);
                mma16816(acc[8 + n16 * 2],     a1r, bf);
                mma16816(acc[8 + n16 * 2 + 1], a1r, bf + 2);
            }
        }

        float cmx[16], cmn[16];
#pragma unroll
        for (int q = 0; q < 16; q++) { cmx[q] = -INFINITY; cmn[q] = INFINITY; }

#pragma unroll
        for (int mb = 0; mb < 2; mb++) {
            const int r0 = i0w + mb * 16 + g, r1 = r0 + 8;
            const float ui0 = uci[r0], ui1 = uci[r1];
            const float vi0 = vcsi[r0], vi1 = vcsi[r1];
            float rx0 = -INFINITY, rn0 = INFINITY, rx1 = -INFINITY, rn1 = INFINITY;
#pragma unroll
            for (int nt = 0; nt < 8; nt++) {
                const int col = j0w + nt * 8 + 2 * tig;
                float2 vj = *(float2*)&vcsj[jo + col];
                float2 uj = *(float2*)&ucj[jo + col];
                const float* G = acc[mb * 8 + nt];
                float e00 = fmaf(s, G[0], vj.x + ui0);
                float e01 = fmaf(s, G[1], vj.y + ui0);
                float e10 = fmaf(s, G[2], vj.x + ui1);
                float e11 = fmaf(s, G[3], vj.y + ui1);
                rx0 = fmaxf(rx0, fmaxf(e00, e01)); rn0 = fminf(rn0, fminf(e00, e01));
                rx1 = fmaxf(rx1, fmaxf(e10, e11)); rn1 = fminf(rn1, fminf(e10, e11));
                float f00 = fmaf(s, G[0], uj.x + vi0);
                float f01 = fmaf(s, G[1], uj.y + vi0);
                float f10 = fmaf(s, G[2], uj.x + vi1);
                float f11 = fmaf(s, G[3], uj.y + vi1);
                cmx[nt * 2]     = fmaxf(cmx[nt * 2],     fmaxf(f00, f10));
                cmn[nt * 2]     = fminf(cmn[nt * 2],     fminf(f00, f10));
                cmx[nt * 2 + 1] = fmaxf(cmx[nt * 2 + 1], fmaxf(f01, f11));
                cmn[nt * 2 + 1] = fminf(cmn[nt * 2 + 1], fminf(f01, f11));
            }
            rxA[mb][0] = fmaxf(rxA[mb][0], rx0); rnA[mb][0] = fminf(rnA[mb][0], rn0);
            rxA[mb][1] = fmaxf(rxA[mb][1], rx1); rnA[mb][1] = fminf(rnA[mb][1], rn1);
        }

        // column (transpose) stats for this j-tile
#pragma unroll
        for (int q = 0; q < 16; q++) {
            float mx = cmx[q], mn = cmn[q];
            mx = fmaxf(mx, __shfl_xor_sync(~0u, mx, 4));
            mx = fmaxf(mx, __shfl_xor_sync(~0u, mx, 8));
            mx = fmaxf(mx, __shfl_xor_sync(~0u, mx, 16));
            mn = fminf(mn, __shfl_xor_sync(~0u, mn, 4));
            mn = fminf(mn, __shfl_xor_sync(~0u, mn, 8));
            mn = fminf(mn, __shfl_xor_sync(~0u, mn, 16));
            cmx[q] = mx; cmn[q] = mn;
        }
        if (g == 0) {
#pragma unroll
            for (int nt = 0; nt < 8; nt++) {
                int col = j0w + nt * 8 + 2 * tig;
                colpx[wi][col] = cmx[nt * 2];         colpn[wi][col] = cmn[nt * 2];
                colpx[wi][col + 1] = cmx[nt * 2 + 1]; colpn[wi][col + 1] = cmn[nt * 2 + 1];
            }
        }
        __syncthreads();
        if (tid < 128) {
            float mx = fmaxf(fmaxf(colpx[0][tid], colpx[1][tid]),
                             fmaxf(colpx[2][tid], colpx[3][tid]));
            float mn = fminf(fminf(colpn[0][tid], colpn[1][tid]),
                             fminf(colpn[2][tid], colpn[3][tid]));
            atomicMax(&g_rkmax[b * T_ + jt + jo + tid], fenc(mx));
            atomicMin(&g_rkmin[b * T_ + jt + jo + tid], fenc(mn));
        }
        __syncthreads();
    }

    // merged row stats -> single atomic per row
#pragma unroll
    for (int mb = 0; mb < 2; mb++) {
#pragma unroll
        for (int rr = 0; rr < 2; rr++) {
            float rx = rxA[mb][rr], rn = rnA[mb][rr];
            rx = fmaxf(rx, __shfl_xor_sync(~0u, rx, 1));
            rx = fmaxf(rx, __shfl_xor_sync(~0u, rx, 2));
            rn = fminf(rn, __shfl_xor_sync(~0u, rn, 1));
            rn = fminf(rn, __shfl_xor_sync(~0u, rn, 2));
            if (tig == 0) {
                const int r = i0w + mb * 16 + g + rr * 8;
                atomicMax(&g_rkmax[b * T_ + it + r], fenc(rx));
                atomicMin(&g_rkmin[b * T_ + it + r], fenc(rn));
            }
        }
    }
}

// ---------------------------------------------------------------------------
// Pass 2: fused attend; per 128-j chunk: E(h0), sm(h0), [E(h1) || P(h0)],
// sm(h1), P(h1).  Softmax folded to fma+ex2.
// Smem: As@0 17408 | Xs0@17408 | Xs1@34816 | csjA@52224 8192
// ---------------------------------------------------------------------------
#define SMEM_ATT 60416
#define LDE_S 65

__global__ __launch_bounds__(256, 2) void attend_mma(const float* __restrict__ x,
                                                     const float* __restrict__ gamma_p,
                                                     float* __restrict__ out) {
    extern __shared__ unsigned char sm[];
    float* csjA = (float*)(sm + 52224);
    float* Sst  = (float*)(sm);
    const uint32_t sa  = sptr(sm);
    const uint32_t sx0 = sa + 17408, sx1 = sa + 34816;

    const int tid = threadIdx.x, lane = tid & 31, wid = tid >> 5;
    const int it = blockIdx.x * 128, b = blockIdx.y;
    const __nv_bfloat16* Xb = g_xbf + (size_t)b * CH_ * T_;
    const float s = g_scal[0], u = g_scal[1], v = g_scal[2], w0 = g_scal[3];
    const float gamma = *gamma_p;
    const float L2E = 1.4426950408889634f;

    {
#pragma unroll
        for (int l = 0; l < 4; l++) {
            int cid = l * 256 + tid;
            int k = cid >> 4, xo = cid & 15;
            cpa16(sa  + (uint32_t)(k * LDT + xo * 8) * 2, Xb + (size_t)k * T_ + it + xo * 8);
            cpa16(sx0 + (uint32_t)(k * LDT + xo * 8) * 2, Xb + (size_t)k * T_ + xo * 8);
        }
        cpa_commit();
    }
#pragma unroll
    for (int l = 0; l < 8; l++)
        csjA[l * 256 + tid] = v * g_colsum[b * T_ + l * 256 + tid];

    const int g = lane >> 2, tig = lane & 3;
    const int r0 = it + wid * 16 + g, r1 = r0 + 8;
    const float mx0 = fdec(g_rkmax[b * T_ + r0]);
    const float mx1 = fdec(g_rkmax[b * T_ + r1]);
    const float R0 = L2E / (mx0 - fdec(g_rkmin[b * T_ + r0]) + 1e-8f);
    const float R1 = L2E / (mx1 - fdec(g_rkmin[b * T_ + r1]) + 1e-8f);
    const float A0 = s * R0, A1 = s * R1;
    const float C0 = (fmaf(u, g_colsum[b * T_ + r0], w0) - mx0) * R0;
    const float C1 = (fmaf(u, g_colsum[b * T_ + r1], w0) - mx1) * R1;
    float den0 = 0.f, den1 = 0.f;

    cpa_wait0();
    __syncthreads();

    uint32_t afr[4][4];
#pragma unroll
    for (int ks = 0; ks < 4; ks++)
        ldsm4t(afr[ks], addrA(sa, lane, ks * 16, wid * 16));

    float accA[8][4];
#pragma unroll
    for (int q = 0; q < 8; q++)
#pragma unroll
        for (int e = 0; e < 4; e++) accA[q][e] = 0.f;

    for (int ch = 0; ch < 16; ch++) {
        const uint32_t bc = (ch & 1) ? sx1 : sx0;
        const int jt = ch * 128;

        if (ch < 15) {
            const uint32_t bn = (ch & 1) ? sx0 : sx1;
#pragma unroll
            for (int l = 0; l < 4; l++) {
                int cid = l * 256 + tid;
                int c = cid >> 4, xo = cid & 15;
                cpa16(bn + (uint32_t)(c * LDT + xo * 8) * 2,
                      Xb + (size_t)c * T_ + jt + 128 + xo * 8);
            }
            cpa_commit();
        }

        float accE[8][4];
        uint32_t ap0[4][4], ap1[4][4];

        // ---- E(h0) ----
#pragma unroll
        for (int q = 0; q < 8; q++)
#pragma unroll
            for (int e = 0; e < 4; e++) accE[q][e] = 0.f;
#pragma unroll
        for (int ks = 0; ks < 4; ks++) {
#pragma unroll
            for (int n16 = 0; n16 < 4; n16++) {
                uint32_t bf[4];
                ldsm4t(bf, addrBt(bc, lane, ks * 16, n16 * 16));
                mma16816(accE[n16 * 2],     afr[ks], bf);
                mma16816(accE[n16 * 2 + 1], afr[ks], bf + 2);
            }
        }
        // ---- softmax(h0) ----
#pragma unroll
        for (int nt = 0; nt < 8; nt++) {
            float2 vj = *(float2*)&csjA[jt + nt * 8 + 2 * tig];
            float p0 = ex2f(fmaf(A0, accE[nt][0], fmaf(R0, vj.x, C0)));
            float p1 = ex2f(fmaf(A0, accE[nt][1], fmaf(R0, vj.y, C0)));
            float p2 = ex2f(fmaf(A1, accE[nt][2], fmaf(R1, vj.x, C1)));
            float p3 = ex2f(fmaf(A1, accE[nt][3], fmaf(R1, vj.y, C1)));
            den0 += p0 + p1;
            den1 += p2 + p3;
            const int ks = nt >> 1, hi = (nt & 1) * 2;
            ap0[ks][hi]     = pk2(p0, p1);
            ap0[ks][hi + 1] = pk2(p2, p3);
        }
        // ---- E(h1) interleaved with P(h0): independent mma streams ----
#pragma unroll
        for (int q = 0; q < 8; q++)
#pragma unroll
            for (int e = 0; e < 4; e++) accE[q][e] = 0.f;
#pragma unroll
        for (int ks = 0; ks < 4; ks++) {
#pragma unroll
            for (int n16 = 0; n16 < 4; n16++) {
                uint32_t be[4], bp[4];
                ldsm4t(be, addrBt(bc, lane, ks * 16, 64 + n16 * 16));
                ldsm4 (bp, addrBp(bc, lane, n16 * 16, ks * 16));
                mma16816(accE[n16 * 2],     afr[ks], be);
                mma16816(accA[n16 * 2],     ap0[ks], bp);
                mma16816(accE[n16 * 2 + 1], afr[ks], be + 2);
                mma16816(accA[n16 * 2 + 1], ap0[ks], bp + 2);
            }
        }
        // ---- softmax(h1) ----
#pragma unroll
        for (int nt = 0; nt < 8; nt++) {
            float2 vj = *(float2*)&csjA[jt + 64 + nt * 8 + 2 * tig];
            float p0 = ex2f(fmaf(A0, accE[nt][0], fmaf(R0, vj.x, C0)));
            float p1 = ex2f(fmaf(A0, accE[nt][1], fmaf(R0, vj.y, C0)));
            float p2 = ex2f(fmaf(A1, accE[nt][2], fmaf(R1, vj.x, C1)));
            float p3 = ex2f(fmaf(A1, accE[nt][3], fmaf(R1, vj.y, C1)));
            den0 += p0 + p1;
            den1 += p2 + p3;
            const int ks = nt >> 1, hi = (nt & 1) * 2;
            ap1[ks][hi]     = pk2(p0, p1);
            ap1[ks][hi + 1] = pk2(p2, p3);
        }
        // ---- P(h1) ----
#pragma unroll
        for (int ks = 0; ks < 4; ks++) {
#pragma unroll
            for (int n16 = 0; n16 < 4; n16++) {
                uint32_t bp[4];
                ldsm4(bp, addrBp(bc, lane, n16 * 16, 64 + ks * 16));
                mma16816(accA[n16 * 2],     ap1[ks], bp);
                mma16816(accA[n16 * 2 + 1], ap1[ks], bp + 2);
            }
        }

        cpa_wait0();
        __syncthreads();
    }

    den0 += __shfl_xor_sync(~0u, den0, 1);
    den0 += __shfl_xor_sync(~0u, den0, 2);
    den1 += __shfl_xor_sync(~0u, den1, 1);
    den1 += __shfl_xor_sync(~0u, den1, 2);
    const float inv0 = gamma / den0, inv1 = gamma / den1;

    const int il0 = wid * 16 + g;
#pragma unroll
    for (int nt = 0; nt < 8; nt++) {
        const int c = nt * 8 + 2 * tig;
        Sst[il0 * LDE_S + c]           = accA[nt][0] * inv0;
        Sst[il0 * LDE_S + c + 1]       = accA[nt][1] * inv0;
        Sst[(il0 + 8) * LDE_S + c]     = accA[nt][2] * inv1;
        Sst[(il0 + 8) * LDE_S + c + 1] = accA[nt][3] * inv1;
    }
    __syncthreads();

    {
        const int i = tid & 127, ch2 = tid >> 7;
#pragma unroll 8
        for (int cc = 0; cc < 32; cc++) {
            const int c = cc * 2 + ch2;
            size_t gi = ((size_t)b * CH_ + c) * T_ + it + i;
            out[gi] = Sst[i * LDE_S + c] + x[gi];
        }
    }
}

// ---------------------------------------------------------------------------
extern "C" void kernel_launch(void* const* d_in, const int* in_sizes, int n_in,
                              void* d_out, int out_size) {
    const float* x     = (const float*)d_in[0];
    const float* w1    = (const float*)d_in[1];
    const float* b1    = (const float*)d_in[2];
    const float* w2    = (const float*)d_in[3];
    const float* b2    = (const float*)d_in[4];
    const float* gamma = (const float*)d_in[5];
    float* out = (float*)d_out;

    cudaFuncSetAttribute(minmax_pair, cudaFuncAttributeMaxDynamicSharedMemorySize, SMEM_MM);
    cudaFuncSetAttribute(attend_mma,  cudaFuncAttributeMaxDynamicSharedMemorySize, SMEM_ATT);

    // 4 launches: attend is correctness-launch #3 -> profile index 5.
    precompute_kernel<<<B_ * T_ / 2 / 256, 256>>>(x, w1, b1, w2, b2);
    minmax_pair<<<dim3(36, B_), 256, SMEM_MM>>>(0);
    minmax_pair<<<dim3(36, B_), 256, SMEM_MM>>>(36);
    attend_mma<<<dim3(T_ / 128, B_), 256, SMEM_ATT>>>(x, gamma, out);
}